// round 10
// baseline (speedup 1.0000x reference)
#include <cuda_runtime.h>
#include <cuda_bf16.h>

#define NATOMS 512
#define NBATCH 16
#define NP 16

__global__ void __launch_bounds__(128) aev_radial_kernel(
    const float* __restrict__ dmat,   // [B, N, N]
    const float* __restrict__ zall,   // [B, N]
    float* __restrict__ out)          // [B, N, 16]
{
    constexpr float RCR       = 5.2f;
    constexpr float PI_OVER_R = 3.14159265358979323846f / 5.2f;
    // log2-domain Gaussian constants: eta=16, shift0=0.9, dshift=0.26875
    constexpr double L2E = 1.4426950408889634;
    constexpr double ETA = 16.0, DSH = 0.26875;
    constexpr float  C2  = (float)(-ETA * L2E);             // -eta*log2e
    constexpr float  A1  = (float)( 2.0 * ETA * DSH * L2E); //  2*eta*dshf*log2e
    constexpr float  A0  = (float)(-ETA * DSH * DSH * L2E); // -eta*dshf^2*log2e
    constexpr double RQd = 0.09913776814937592;             // exp(-2*eta*dshf^2)
    constexpr float  GSP = 1.075f;                          // 4*dshf

    // per-group constants (compile-time immediates)
    // q_k = q * RQ^{4k};  t1_k = s*RQ^{8k+1} (=g2/g0);  t2_k = s*RQ^{8k+3} (=g3/g1)
    const float RQ4K[4] = {1.0f,
                           (float)(RQd*RQd*RQd*RQd),
                           (float)(RQd*RQd*RQd*RQd*RQd*RQd*RQd*RQd),
                           (float)(RQd*RQd*RQd*RQd*RQd*RQd*RQd*RQd*RQd*RQd*RQd*RQd)};
    const float T1K[4]  = {(float)pow(RQd, 1.0), (float)pow(RQd, 9.0),
                           (float)pow(RQd, 17.0), (float)pow(RQd, 25.0)};
    const float T2K[4]  = {(float)pow(RQd, 3.0), (float)pow(RQd, 11.0),
                           (float)pow(RQd, 19.0), (float)pow(RQd, 27.0)};

    const int warp_g = (blockIdx.x * blockDim.x + threadIdx.x) >> 5;  // 0..4095
    const int lane   = threadIdx.x & 31;
    const int b      = warp_g >> 8;          // batch 0..15
    const int i0     = warp_g & 255;         // base row within batch

    const float* __restrict__ zrow = zall + (size_t)b * NATOMS;
    const unsigned FULL = 0xffffffffu;

    // each warp computes two rows: i0 and i0+256 (same batch -> shared z row)
#pragma unroll 1
    for (int half = 0; half < 2; ++half) {
        const int wg = b * NATOMS + i0 + half * 256;
        const float* __restrict__ row = dmat + (size_t)wg * NATOMS;

        float acc[NP];
#pragma unroll
        for (int p = 0; p < NP; ++p) acc[p] = 0.0f;

#pragma unroll
        for (int it = 0; it < 4; ++it) {
            const int j0 = it * 128 + lane * 4;
            const float4 dv = *reinterpret_cast<const float4*>(row  + j0);
            const float4 zv = *reinterpret_cast<const float4*>(zrow + j0);
            const float dd[4] = {dv.x, dv.y, dv.z, dv.w};
            const float zz[4] = {zv.x, zv.y, zv.z, zv.w};

#pragma unroll
            for (int e = 0; e < 4; ++e) {
                const float dj = dd[e];
                // cutoff weight; mask (0 < d < RCR) as one range-compare
                float c;
                asm("cos.approx.ftz.f32 %0, %1;" : "=f"(c) : "f"(dj * PI_OVER_R));
                const float hz = 0.5f * zz[e];
                const float wz = fmaf(hz, c, hz);          // z*(0.5*cos+0.5)
                const float w  = (fabsf(dj - 2.6f) < 2.6f) ? wz : 0.0f;

                // clamp Gaussian path only (masked d>RCR would overflow s)
                const float dg = fminf(dj, RCR);
                const float u0 = dg - 0.9f;

                // one ex2 anchors all step ratios
                float q;
                asm("ex2.approx.ftz.f32 %0, %1;" : "=f"(q) : "f"(fmaf(A1, u0, A0)));
                const float s = q * q;                      // <= 2^103.4, finite

                // 4 independent groups of 4 shifts
#pragma unroll
                for (int k = 0; k < 4; ++k) {
                    const float uk = u0 - (float)k * GSP;   // independent (imm)
                    float g0;
                    asm("ex2.approx.ftz.f32 %0, %1;"
                        : "=f"(g0) : "f"((C2 * uk) * uk));
                    const float qk = q * RQ4K[k];           // imm mul
                    const float g1 = g0 * qk;
                    const float g2 = g0 * (s * T1K[k]);     // imm mul + mul
                    const float g3 = g1 * (s * T2K[k]);
                    acc[4*k + 0] = fmaf(w, g0, acc[4*k + 0]);
                    acc[4*k + 1] = fmaf(w, g1, acc[4*k + 1]);
                    acc[4*k + 2] = fmaf(w, g2, acc[4*k + 2]);
                    acc[4*k + 3] = fmaf(w, g3, acc[4*k + 3]);
                }
            }
        }

        // halving reduction: 16 regs -> 1 reg across 32 lanes
        float a[NP];
#pragma unroll
        for (int p = 0; p < NP; ++p) a[p] = acc[p];

#pragma unroll
        for (int v = 0; v < 8; ++v) {
            const bool hi = (lane & 16);
            const float send = hi ? a[v] : a[v + 8];
            const float r = __shfl_xor_sync(FULL, send, 16);
            a[v] = (hi ? a[v + 8] : a[v]) + r;
        }
#pragma unroll
        for (int v = 0; v < 4; ++v) {
            const bool hi = (lane & 8);
            const float send = hi ? a[v] : a[v + 4];
            const float r = __shfl_xor_sync(FULL, send, 8);
            a[v] = (hi ? a[v + 4] : a[v]) + r;
        }
#pragma unroll
        for (int v = 0; v < 2; ++v) {
            const bool hi = (lane & 4);
            const float send = hi ? a[v] : a[v + 2];
            const float r = __shfl_xor_sync(FULL, send, 4);
            a[v] = (hi ? a[v + 2] : a[v]) + r;
        }
        {
            const bool hi = (lane & 2);
            const float send = hi ? a[0] : a[1];
            const float r = __shfl_xor_sync(FULL, send, 2);
            a[0] = (hi ? a[1] : a[0]) + r;
        }
        a[0] += __shfl_xor_sync(FULL, a[0], 1);

        if ((lane & 1) == 0) {
            out[(size_t)wg * NP + ((lane >> 1) & 15)] = a[0];
        }
    }
}

extern "C" void kernel_launch(void* const* d_in, const int* in_sizes, int n_in,
                              void* d_out, int out_size)
{
    const float* dmat = (const float*)d_in[0];   // [16, 512, 512] float32
    const float* zall = (const float*)d_in[1];   // [16, 512] float32
    float* out        = (float*)d_out;           // [16, 512, 16] float32

    // 1024 blocks x 128 threads = 4096 warps; each warp does 2 rows.
    // Single balanced wave; scalar math -> lower regs, higher residency.
    aev_radial_kernel<<<1024, 128>>>(dmat, zall, out);
}

// round 11
// speedup vs baseline: 11.3836x; 11.3836x over previous
#include <cuda_runtime.h>
#include <cuda_bf16.h>

#define NATOMS 512
#define NBATCH 16
#define NP 16

// ---- compile-time constants (NO runtime pow — that caused the R9 regression) ----
constexpr double RQd = 0.09913776814937592;   // exp(-2*eta*dshf^2)
constexpr double rqp(int n) {                 // RQd^n at compile time
    double r = 1.0;
    for (int i = 0; i < n; ++i) r *= RQd;
    return r;
}
// q_k = q * RQ^{4k};  g2/g0 = s*RQ^{8k+1};  g3/g1 = s*RQ^{8k+3}
constexpr float RQ4_1 = (float)rqp(4),  RQ4_2 = (float)rqp(8),  RQ4_3 = (float)rqp(12);
constexpr float T1_0  = (float)rqp(1),  T1_1  = (float)rqp(9),
                T1_2  = (float)rqp(17), T1_3  = (float)rqp(25);
constexpr float T2_0  = (float)rqp(3),  T2_1  = (float)rqp(11),
                T2_2  = (float)rqp(19), T2_3  = (float)rqp(27);

__global__ void __launch_bounds__(128) aev_radial_kernel(
    const float* __restrict__ dmat,   // [B, N, N]
    const float* __restrict__ zall,   // [B, N]
    float* __restrict__ out)          // [B, N, 16]
{
    constexpr float RCR       = 5.2f;
    constexpr float PI_OVER_R = 3.14159265358979323846f / 5.2f;
    constexpr double L2E = 1.4426950408889634;
    constexpr double ETA = 16.0, DSH = 0.26875;
    constexpr float  C2  = (float)(-ETA * L2E);             // -eta*log2e
    constexpr float  A1  = (float)( 2.0 * ETA * DSH * L2E); //  2*eta*dshf*log2e
    constexpr float  A0  = (float)(-ETA * DSH * DSH * L2E); // -eta*dshf^2*log2e
    constexpr float  GSP = 1.075f;                          // 4*dshf

    const int warp_g = (blockIdx.x * blockDim.x + threadIdx.x) >> 5;  // 0..4095
    const int lane   = threadIdx.x & 31;
    const int b      = warp_g >> 8;          // batch 0..15
    const int i0     = warp_g & 255;         // base row within batch

    const float* __restrict__ zrow = zall + (size_t)b * NATOMS;
    const unsigned FULL = 0xffffffffu;

    // each warp computes two rows: i0 and i0+256 (same batch -> shared z row)
#pragma unroll 1
    for (int half = 0; half < 2; ++half) {
        const int wg = b * NATOMS + i0 + half * 256;
        const float* __restrict__ row = dmat + (size_t)wg * NATOMS;

        float acc[NP];
#pragma unroll
        for (int p = 0; p < NP; ++p) acc[p] = 0.0f;

#pragma unroll
        for (int it = 0; it < 4; ++it) {
            const int j0 = it * 128 + lane * 4;
            const float4 dv = *reinterpret_cast<const float4*>(row  + j0);
            const float4 zv = *reinterpret_cast<const float4*>(zrow + j0);
            const float dd[4] = {dv.x, dv.y, dv.z, dv.w};
            const float zz[4] = {zv.x, zv.y, zv.z, zv.w};

#pragma unroll
            for (int e = 0; e < 4; ++e) {
                const float dj = dd[e];
                // cutoff weight; mask (0 < d < RCR) as one range-compare
                float c;
                asm("cos.approx.ftz.f32 %0, %1;" : "=f"(c) : "f"(dj * PI_OVER_R));
                const float hz = 0.5f * zz[e];
                const float wz = fmaf(hz, c, hz);          // z*(0.5*cos+0.5)
                const float w  = (fabsf(dj - 2.6f) < 2.6f) ? wz : 0.0f;

                // clamp Gaussian path only (masked d>RCR would overflow s)
                const float dg = fminf(dj, RCR);
                const float u0 = dg - 0.9f;

                // one ex2 anchors all step ratios
                float q;
                asm("ex2.approx.ftz.f32 %0, %1;" : "=f"(q) : "f"(fmaf(A1, u0, A0)));
                const float s = q * q;                      // <= 2^103.4, finite

                // 4 independent groups of 4 shifts; all imm-form multiplies
                float g0, v1, v2, v3;

                // k = 0
                asm("ex2.approx.ftz.f32 %0, %1;" : "=f"(g0) : "f"((C2 * u0) * u0));
                v1 = g0 * q;
                v2 = g0 * (s * T1_0);
                v3 = v1 * (s * T2_0);
                acc[0] = fmaf(w, g0, acc[0]);
                acc[1] = fmaf(w, v1, acc[1]);
                acc[2] = fmaf(w, v2, acc[2]);
                acc[3] = fmaf(w, v3, acc[3]);
                // k = 1
                {
                    const float uk = u0 - GSP;
                    asm("ex2.approx.ftz.f32 %0, %1;" : "=f"(g0) : "f"((C2 * uk) * uk));
                    v1 = g0 * (q * RQ4_1);
                    v2 = g0 * (s * T1_1);
                    v3 = v1 * (s * T2_1);
                    acc[4] = fmaf(w, g0, acc[4]);
                    acc[5] = fmaf(w, v1, acc[5]);
                    acc[6] = fmaf(w, v2, acc[6]);
                    acc[7] = fmaf(w, v3, acc[7]);
                }
                // k = 2
                {
                    const float uk = u0 - 2.0f * GSP;
                    asm("ex2.approx.ftz.f32 %0, %1;" : "=f"(g0) : "f"((C2 * uk) * uk));
                    v1 = g0 * (q * RQ4_2);
                    v2 = g0 * (s * T1_2);
                    v3 = v1 * (s * T2_2);
                    acc[8]  = fmaf(w, g0, acc[8]);
                    acc[9]  = fmaf(w, v1, acc[9]);
                    acc[10] = fmaf(w, v2, acc[10]);
                    acc[11] = fmaf(w, v3, acc[11]);
                }
                // k = 3
                {
                    const float uk = u0 - 3.0f * GSP;
                    asm("ex2.approx.ftz.f32 %0, %1;" : "=f"(g0) : "f"((C2 * uk) * uk));
                    v1 = g0 * (q * RQ4_3);
                    v2 = g0 * (s * T1_3);
                    v3 = v1 * (s * T2_3);
                    acc[12] = fmaf(w, g0, acc[12]);
                    acc[13] = fmaf(w, v1, acc[13]);
                    acc[14] = fmaf(w, v2, acc[14]);
                    acc[15] = fmaf(w, v3, acc[15]);
                }
            }
        }

        // halving reduction: 16 regs -> 1 reg across 32 lanes
        float a[NP];
#pragma unroll
        for (int p = 0; p < NP; ++p) a[p] = acc[p];

#pragma unroll
        for (int v = 0; v < 8; ++v) {
            const bool hi = (lane & 16);
            const float send = hi ? a[v] : a[v + 8];
            const float r = __shfl_xor_sync(FULL, send, 16);
            a[v] = (hi ? a[v + 8] : a[v]) + r;
        }
#pragma unroll
        for (int v = 0; v < 4; ++v) {
            const bool hi = (lane & 8);
            const float send = hi ? a[v] : a[v + 4];
            const float r = __shfl_xor_sync(FULL, send, 8);
            a[v] = (hi ? a[v + 4] : a[v]) + r;
        }
#pragma unroll
        for (int v = 0; v < 2; ++v) {
            const bool hi = (lane & 4);
            const float send = hi ? a[v] : a[v + 2];
            const float r = __shfl_xor_sync(FULL, send, 4);
            a[v] = (hi ? a[v + 2] : a[v]) + r;
        }
        {
            const bool hi = (lane & 2);
            const float send = hi ? a[0] : a[1];
            const float r = __shfl_xor_sync(FULL, send, 2);
            a[0] = (hi ? a[1] : a[0]) + r;
        }
        a[0] += __shfl_xor_sync(FULL, a[0], 1);

        if ((lane & 1) == 0) {
            out[(size_t)wg * NP + ((lane >> 1) & 15)] = a[0];
        }
    }
}

extern "C" void kernel_launch(void* const* d_in, const int* in_sizes, int n_in,
                              void* d_out, int out_size)
{
    const float* dmat = (const float*)d_in[0];   // [16, 512, 512] float32
    const float* zall = (const float*)d_in[1];   // [16, 512] float32
    float* out        = (float*)d_out;           // [16, 512, 16] float32

    // 1024 blocks x 128 threads = 4096 warps; each warp does 2 rows.
    // Single balanced wave; all-scalar math, all constants compile-time.
    aev_radial_kernel<<<1024, 128>>>(dmat, zall, out);
}